// round 3
// baseline (speedup 1.0000x reference)
#include <cuda_runtime.h>
#include <cuda_bf16.h>
#include <math.h>

typedef __nv_bfloat16 bf16;

#define BATCH 8192
#define SDIM  268
#define HDIM  1024
#define RB    8
#define ADIM  256
#define ZDIM  8
#define PDIM  4
#define EDIM  4
#define KX    272   /* S+2 padded to multiple of 16 */

#define CDIV(a,b) (((a)+(b)-1)/(b))

#define EPI_NONE 0
#define EPI_RELU 1
#define EPI_TANH 2

// ---------------------------------------------------------------------------
// Scratch (static __device__ arrays; no allocation anywhere)
// ---------------------------------------------------------------------------
__device__ __align__(16) float g_x [BATCH*KX];
__device__ __align__(16) float g_h [BATCH*HDIM];
__device__ __align__(16) float g_u [BATCH*HDIM];
__device__ __align__(16) float g_v2[BATCH*ADIM];
__device__ __align__(16) float g_dh[BATCH*ADIM];
__device__ __align__(16) float g_dloc[BATCH*ZDIM];

__device__ __align__(16) bf16 g_W0h[HDIM*KX],       g_W0l[HDIM*KX];
__device__ __align__(16) bf16 g_W1h[RB*HDIM*HDIM],  g_W1l[RB*HDIM*HDIM];
__device__ __align__(16) bf16 g_W2h[RB*HDIM*HDIM],  g_W2l[RB*HDIM*HDIM];
__device__ __align__(16) bf16 g_Wfh[SDIM*HDIM],     g_Wfl[SDIM*HDIM];
__device__ __align__(16) bf16 g_TIh[ADIM*ADIM],     g_TIl[ADIM*ADIM];
__device__ __align__(16) bf16 g_TOh[ADIM*ADIM],     g_TOl[ADIM*ADIM];

// ---------------------------------------------------------------------------
// Helpers
// ---------------------------------------------------------------------------
__device__ __forceinline__ float tanh_fast(float x) {
    float e = __expf(2.0f * x);
    return 1.0f - __fdividef(2.0f, e + 1.0f);   // NaN-safe for e -> inf or 0
}

__device__ __forceinline__ void ldm4(unsigned r[4], unsigned addr) {
    asm volatile("ldmatrix.sync.aligned.m8n8.x4.shared.b16 {%0,%1,%2,%3}, [%4];"
                 : "=r"(r[0]), "=r"(r[1]), "=r"(r[2]), "=r"(r[3]) : "r"(addr));
}
__device__ __forceinline__ void ldm2(unsigned r[2], unsigned addr) {
    asm volatile("ldmatrix.sync.aligned.m8n8.x2.shared.b16 {%0,%1}, [%2];"
                 : "=r"(r[0]), "=r"(r[1]) : "r"(addr));
}
__device__ __forceinline__ void mma_bf16(float c[4], const unsigned a[4], const unsigned b[2]) {
    asm volatile(
        "mma.sync.aligned.m16n8k16.row.col.f32.bf16.bf16.f32 "
        "{%0,%1,%2,%3}, {%4,%5,%6,%7}, {%8,%9}, {%0,%1,%2,%3};"
        : "+f"(c[0]), "+f"(c[1]), "+f"(c[2]), "+f"(c[3])
        : "r"(a[0]), "r"(a[1]), "r"(a[2]), "r"(a[3]), "r"(b[0]), "r"(b[1]));
}

// ---------------------------------------------------------------------------
// Main GEMM: C(MxN) = act( A(MxK,f32) @ B^T + bias [+ addend] )
// B given pre-split as bf16 hi/lo, row-major [N][K] (ldb).
// A split to bf16 hi/lo on the fly while staging into SMEM.
// 3-MMA bf16 emulation: hi*hi + hi*lo + lo*hi  (error ~2^-18).
// CTA tile 128x128, BK=16, 256 threads, warp grid 2(m) x 4(n), warp tile 64x32.
// ---------------------------------------------------------------------------
__global__ void __launch_bounds__(256, 1)
gemm_bf16x3(const float* __restrict__ A, int lda,
            const bf16* __restrict__ Bhi, const bf16* __restrict__ Blo, int ldb,
            const float* __restrict__ bias, const float* __restrict__ addend,
            float* __restrict__ C, int ldc, int N, int K, int epi)
{
    __shared__ __align__(16) bf16 sAh[2][128][24];   // 48B row stride: conflict-free ldmatrix
    __shared__ __align__(16) bf16 sAl[2][128][24];
    __shared__ __align__(16) bf16 sBh[2][128][16];
    __shared__ __align__(16) bf16 sBl[2][128][16];

    const int tid    = threadIdx.x;
    const int lane   = tid & 31;
    const int wid    = tid >> 5;
    const int warpM  = wid >> 2;        // 0..1
    const int warpN  = wid & 3;         // 0..3
    const int blockM = blockIdx.y * 128;
    const int blockN = blockIdx.x * 128;

    // staging: thread t loads row t/2, 8 elements at col (t&1)*8
    const int sRow = tid >> 1;
    const int sCol = (tid & 1) * 8;

    const float* Aptr = A + (size_t)(blockM + sRow) * lda + sCol;
    const int    nG   = blockN + sRow;
    const bool   bOk  = nG < N;
    const bf16*  Bhp  = Bhi + (size_t)nG * ldb + sCol;
    const bf16*  Blp  = Blo + (size_t)nG * ldb + sCol;

    const unsigned baseAh = (unsigned)__cvta_generic_to_shared(&sAh[0][0][0]);
    const unsigned baseAl = (unsigned)__cvta_generic_to_shared(&sAl[0][0][0]);
    const unsigned baseBh = (unsigned)__cvta_generic_to_shared(&sBh[0][0][0]);
    const unsigned baseBl = (unsigned)__cvta_generic_to_shared(&sBl[0][0][0]);

    unsigned aOff[4], bOff[4];
    {
        const int r  = lane & 15;
        const int ko = (lane >> 4) * 8;
        #pragma unroll
        for (int mt = 0; mt < 4; ++mt)
            aOff[mt] = (unsigned)(((warpM * 64 + mt * 16 + r) * 24 + ko) * 2);
        const int rb  = lane & 7;
        const int kob = ((lane >> 3) & 1) * 8;
        #pragma unroll
        for (int nt = 0; nt < 4; ++nt)
            bOff[nt] = (unsigned)(((warpN * 32 + nt * 8 + rb) * 16 + kob) * 2);
    }

    float acc[4][4][4];
    #pragma unroll
    for (int mt = 0; mt < 4; ++mt)
        #pragma unroll
        for (int nt = 0; nt < 4; ++nt)
            #pragma unroll
            for (int i = 0; i < 4; ++i) acc[mt][nt][i] = 0.0f;

    float4 ra0, ra1;
    uint4  rbh, rbl;

    auto loadRegs = [&](int k0) {
        ra0 = *(const float4*)(Aptr + k0);
        ra1 = *(const float4*)(Aptr + k0 + 4);
        if (bOk) {
            rbh = *(const uint4*)(Bhp + k0);
            rbl = *(const uint4*)(Blp + k0);
        } else {
            rbh = make_uint4(0u,0u,0u,0u);
            rbl = make_uint4(0u,0u,0u,0u);
        }
    };
    auto storeStage = [&](int buf) {
        float av[8] = {ra0.x, ra0.y, ra0.z, ra0.w, ra1.x, ra1.y, ra1.z, ra1.w};
        __nv_bfloat162* dh = (__nv_bfloat162*)&sAh[buf][sRow][sCol];
        __nv_bfloat162* dl = (__nv_bfloat162*)&sAl[buf][sRow][sCol];
        #pragma unroll
        for (int j = 0; j < 4; ++j) {
            float x0 = av[2*j], x1 = av[2*j+1];
            bf16 h0 = __float2bfloat16(x0);
            bf16 h1 = __float2bfloat16(x1);
            bf16 l0 = __float2bfloat16(x0 - __bfloat162float(h0));
            bf16 l1 = __float2bfloat16(x1 - __bfloat162float(h1));
            dh[j] = __halves2bfloat162(h0, h1);
            dl[j] = __halves2bfloat162(l0, l1);
        }
        *(uint4*)&sBh[buf][sRow][sCol] = rbh;
        *(uint4*)&sBl[buf][sRow][sCol] = rbl;
    };

    const int nk = K / 16;
    loadRegs(0);
    storeStage(0);
    __syncthreads();

    for (int kt = 0; kt < nk; ++kt) {
        const int  buf  = kt & 1;
        const bool more = (kt + 1) < nk;
        if (more) loadRegs((kt + 1) * 16);

        unsigned Ah[4][4], Al[4][4], Bh[4][2], Bl[4][2];
        const unsigned offA = (unsigned)(buf * (128 * 24 * 2));
        const unsigned offB = (unsigned)(buf * (128 * 16 * 2));
        #pragma unroll
        for (int mt = 0; mt < 4; ++mt) {
            ldm4(Ah[mt], baseAh + offA + aOff[mt]);
            ldm4(Al[mt], baseAl + offA + aOff[mt]);
        }
        #pragma unroll
        for (int nt = 0; nt < 4; ++nt) {
            ldm2(Bh[nt], baseBh + offB + bOff[nt]);
            ldm2(Bl[nt], baseBl + offB + bOff[nt]);
        }
        #pragma unroll
        for (int mt = 0; mt < 4; ++mt)
            #pragma unroll
            for (int nt = 0; nt < 4; ++nt) {
                mma_bf16(acc[mt][nt], Ah[mt], Bh[nt]);
                mma_bf16(acc[mt][nt], Ah[mt], Bl[nt]);
                mma_bf16(acc[mt][nt], Al[mt], Bh[nt]);
            }

        if (more) storeStage(buf ^ 1);
        __syncthreads();
    }

    // epilogue
    const int g = lane >> 2, q = lane & 3;
    #pragma unroll
    for (int mt = 0; mt < 4; ++mt) {
        #pragma unroll
        for (int nt = 0; nt < 4; ++nt) {
            const int row = blockM + warpM * 64 + mt * 16 + g;
            const int col = blockN + warpN * 32 + nt * 8 + q * 2;
            const bool c0 = col < N, c1 = (col + 1) < N;
            const float b0v = c0 ? bias[col] : 0.0f;
            const float b1v = c1 ? bias[col + 1] : 0.0f;
            #pragma unroll
            for (int rr = 0; rr < 2; ++rr) {
                const int r = row + rr * 8;
                float v0 = acc[mt][nt][rr * 2 + 0] + b0v;
                float v1 = acc[mt][nt][rr * 2 + 1] + b1v;
                if (addend) {
                    if (c0) v0 += addend[(size_t)r * ldc + col];
                    if (c1) v1 += addend[(size_t)r * ldc + col + 1];
                }
                if (epi == EPI_RELU)      { v0 = fmaxf(v0, 0.0f); v1 = fmaxf(v1, 0.0f); }
                else if (epi == EPI_TANH) { v0 = tanh_fast(v0);   v1 = tanh_fast(v1);   }
                if (c0) C[(size_t)r * ldc + col]     = v0;
                if (c1) C[(size_t)r * ldc + col + 1] = v1;
            }
        }
    }
}

// ---------------------------------------------------------------------------
// Prologue kernels
// ---------------------------------------------------------------------------
__global__ void split4_kernel(const float* __restrict__ src,
                              bf16* __restrict__ hi, bf16* __restrict__ lo, int n4)
{
    int i = blockIdx.x * blockDim.x + threadIdx.x;
    if (i >= n4) return;
    float4 v = ((const float4*)src)[i];
    float a[4] = {v.x, v.y, v.z, v.w};
    __nv_bfloat162* dh = (__nv_bfloat162*)hi;
    __nv_bfloat162* dl = (__nv_bfloat162*)lo;
    bf16 h[4], l[4];
    #pragma unroll
    for (int j = 0; j < 4; ++j) {
        h[j] = __float2bfloat16(a[j]);
        l[j] = __float2bfloat16(a[j] - __bfloat162float(h[j]));
    }
    dh[2*i]   = __halves2bfloat162(h[0], h[1]);
    dh[2*i+1] = __halves2bfloat162(h[2], h[3]);
    dl[2*i]   = __halves2bfloat162(l[0], l[1]);
    dl[2*i+1] = __halves2bfloat162(l[2], l[3]);
}

__global__ void splitW0_kernel(const float* __restrict__ W0,
                               bf16* __restrict__ hi, bf16* __restrict__ lo)
{
    int i = blockIdx.x * blockDim.x + threadIdx.x;
    if (i >= HDIM * KX) return;
    int row = i / KX, c = i % KX;
    float v = (c < SDIM + 2) ? W0[row * (SDIM + 2) + c] : 0.0f;
    bf16 h = __float2bfloat16(v);
    hi[i] = h;
    lo[i] = __float2bfloat16(v - __bfloat162float(h));
}

__global__ void buildx_kernel(const float* __restrict__ state,
                              const float* __restrict__ t,
                              float* __restrict__ x)
{
    int i = blockIdx.x * blockDim.x + threadIdx.x;
    if (i >= BATCH * KX) return;
    int b = i / KX, c = i % KX;
    float v;
    if (c < SDIM) v = state[b * SDIM + c];
    else if (c == SDIM)     { float ang = t[0] * 0.26179938779914943654f; v = sinf(ang); }
    else if (c == SDIM + 1) { float ang = t[0] * 0.26179938779914943654f; v = cosf(ang); }
    else v = 0.0f;
    x[i] = v;
}

// ---------------------------------------------------------------------------
// Tiny loc path (exact fp32)
// ---------------------------------------------------------------------------
__global__ void loc_kernel(const float* __restrict__ state,
                           const float* __restrict__ loc_proj_w, const float* __restrict__ loc_proj_b,
                           const float* __restrict__ lp_in_w,    const float* __restrict__ lp_in_b,
                           const float* __restrict__ lp_out_w,   const float* __restrict__ lp_out_b,
                           const float* __restrict__ loc_back_w, const float* __restrict__ loc_back_b,
                           float* __restrict__ dloc)
{
    int b = blockIdx.x * blockDim.x + threadIdx.x;
    if (b >= BATCH) return;
    float loc[ZDIM];
    #pragma unroll
    for (int z = 0; z < ZDIM; ++z) loc[z] = state[b * SDIM + ADIM + z];
    float lp[EDIM];
    #pragma unroll
    for (int e = 0; e < EDIM; ++e) {
        float s = loc_proj_b[e];
        #pragma unroll
        for (int z = 0; z < ZDIM; ++z) s += loc_proj_w[e * ZDIM + z] * loc[z];
        lp[e] = s;
    }
    float v[EDIM];
    #pragma unroll
    for (int e = 0; e < EDIM; ++e) {
        float s = lp_in_b[2 * EDIM + e];
        #pragma unroll
        for (int j = 0; j < EDIM; ++j) s += lp_in_w[(2 * EDIM + e) * EDIM + j] * lp[j];
        v[e] = s;
    }
    float d[EDIM];
    #pragma unroll
    for (int e = 0; e < EDIM; ++e) {
        float s = lp_out_b[e];
        #pragma unroll
        for (int j = 0; j < EDIM; ++j) s += lp_out_w[e * EDIM + j] * v[j];
        d[e] = s - lp[e];
    }
    #pragma unroll
    for (int z = 0; z < ZDIM; ++z) {
        float s = loc_back_b[z];
        #pragma unroll
        for (int e = 0; e < EDIM; ++e) s += loc_back_w[z * EDIM + e] * d[e];
        dloc[b * ZDIM + z] = s;
    }
}

// out = core + 0.1 * delta
__global__ void combine_kernel(float* __restrict__ out,
                               const float* __restrict__ state,
                               const float* __restrict__ dh,
                               const float* __restrict__ dloc)
{
    int i = blockIdx.x * blockDim.x + threadIdx.x;
    if (i >= BATCH * SDIM) return;
    int b = i / SDIM, j = i % SDIM;
    float o = out[i];
    if (j < ADIM)              o += 0.1f * (dh[b * ADIM + j] - state[i]);
    else if (j < ADIM + ZDIM)  o += 0.1f * dloc[b * ZDIM + (j - ADIM)];
    out[i] = o;
}

// ---------------------------------------------------------------------------
// Launch
// ---------------------------------------------------------------------------
extern "C" void kernel_launch(void* const* d_in, const int* in_sizes, int n_in,
                              void* d_out, int out_size)
{
    const float* t          = (const float*)d_in[0];
    const float* state      = (const float*)d_in[1];
    const float* W0         = (const float*)d_in[2];
    const float* b0         = (const float*)d_in[3];
    const float* rW1        = (const float*)d_in[4];
    const float* rb1        = (const float*)d_in[5];
    const float* rW2        = (const float*)d_in[6];
    const float* rb2        = (const float*)d_in[7];
    const float* Wf         = (const float*)d_in[8];
    const float* bf_        = (const float*)d_in[9];
    const float* lp_in_w    = (const float*)d_in[10];
    const float* lp_in_b    = (const float*)d_in[11];
    const float* lp_out_w   = (const float*)d_in[12];
    const float* lp_out_b   = (const float*)d_in[13];
    const float* ta_in_w    = (const float*)d_in[14];
    const float* ta_in_b    = (const float*)d_in[15];
    const float* ta_out_w   = (const float*)d_in[16];
    const float* ta_out_b   = (const float*)d_in[17];
    const float* loc_proj_w = (const float*)d_in[18];
    const float* loc_proj_b = (const float*)d_in[19];
    const float* loc_back_w = (const float*)d_in[20];
    const float* loc_back_b = (const float*)d_in[21];
    float* out = (float*)d_out;

    float *x, *h, *u, *v2, *dh, *dloc;
    bf16 *W0h, *W0l, *W1h, *W1l, *W2h, *W2l, *Wfh, *Wfl, *TIh, *TIl, *TOh, *TOl;
    cudaGetSymbolAddress((void**)&x,   g_x);
    cudaGetSymbolAddress((void**)&h,   g_h);
    cudaGetSymbolAddress((void**)&u,   g_u);
    cudaGetSymbolAddress((void**)&v2,  g_v2);
    cudaGetSymbolAddress((void**)&dh,  g_dh);
    cudaGetSymbolAddress((void**)&dloc,g_dloc);
    cudaGetSymbolAddress((void**)&W0h, g_W0h);  cudaGetSymbolAddress((void**)&W0l, g_W0l);
    cudaGetSymbolAddress((void**)&W1h, g_W1h);  cudaGetSymbolAddress((void**)&W1l, g_W1l);
    cudaGetSymbolAddress((void**)&W2h, g_W2h);  cudaGetSymbolAddress((void**)&W2l, g_W2l);
    cudaGetSymbolAddress((void**)&Wfh, g_Wfh);  cudaGetSymbolAddress((void**)&Wfl, g_Wfl);
    cudaGetSymbolAddress((void**)&TIh, g_TIh);  cudaGetSymbolAddress((void**)&TIl, g_TIl);
    cudaGetSymbolAddress((void**)&TOh, g_TOh);  cudaGetSymbolAddress((void**)&TOl, g_TOl);

    // --- prologue: split weights to bf16 hi/lo, build x ---
    {
        int n4;
        n4 = (RB * HDIM * HDIM) / 4;
        split4_kernel<<<CDIV(n4, 256), 256>>>(rW1, W1h, W1l, n4);
        split4_kernel<<<CDIV(n4, 256), 256>>>(rW2, W2h, W2l, n4);
        n4 = (SDIM * HDIM) / 4;
        split4_kernel<<<CDIV(n4, 256), 256>>>(Wf, Wfh, Wfl, n4);
        n4 = (ADIM * ADIM) / 4;
        split4_kernel<<<CDIV(n4, 256), 256>>>(ta_in_w + 2 * ADIM * ADIM, TIh, TIl, n4);
        split4_kernel<<<CDIV(n4, 256), 256>>>(ta_out_w, TOh, TOl, n4);
        splitW0_kernel<<<CDIV(HDIM * KX, 256), 256>>>(W0, W0h, W0l);
        buildx_kernel<<<CDIV(BATCH * KX, 256), 256>>>(state, t, x);
    }

    // --- main chain ---
    dim3 blk(256);
    dim3 gH(HDIM / 128, BATCH / 128);           // N=1024
    gemm_bf16x3<<<gH, blk>>>(x, KX, W0h, W0l, KX, b0, nullptr, h, HDIM,
                             HDIM, KX, EPI_RELU);

    for (int i = 0; i < RB; ++i) {
        const size_t wo = (size_t)i * HDIM * HDIM;
        gemm_bf16x3<<<gH, blk>>>(h, HDIM, W1h + wo, W1l + wo, HDIM,
                                 rb1 + i * HDIM, nullptr, u, HDIM,
                                 HDIM, HDIM, EPI_TANH);
        gemm_bf16x3<<<gH, blk>>>(u, HDIM, W2h + wo, W2l + wo, HDIM,
                                 rb2 + i * HDIM, h, h, HDIM,
                                 HDIM, HDIM, EPI_TANH);
    }

    dim3 gF(CDIV(SDIM, 128), BATCH / 128);      // N=268 -> 3 tiles
    gemm_bf16x3<<<gF, blk>>>(h, HDIM, Wfh, Wfl, HDIM, bf_, nullptr, out, SDIM,
                             SDIM, HDIM, EPI_NONE);

    // --- independent side path ---
    dim3 gT(ADIM / 128, BATCH / 128);           // N=256
    gemm_bf16x3<<<gT, blk>>>(state, SDIM, TIh, TIl, ADIM, ta_in_b + 2 * ADIM,
                             nullptr, v2, ADIM, ADIM, ADIM, EPI_NONE);
    gemm_bf16x3<<<gT, blk>>>(v2, ADIM, TOh, TOl, ADIM, ta_out_b,
                             nullptr, dh, ADIM, ADIM, ADIM, EPI_NONE);
    loc_kernel<<<CDIV(BATCH, 256), 256>>>(state, loc_proj_w, loc_proj_b,
                                          lp_in_w, lp_in_b, lp_out_w, lp_out_b,
                                          loc_back_w, loc_back_b, dloc);

    // --- final combine ---
    combine_kernel<<<CDIV(BATCH * SDIM, 256), 256>>>(out, state, dh, dloc);
}

// round 6
// speedup vs baseline: 1.2185x; 1.2185x over previous
#include <cuda_runtime.h>
#include <cuda_bf16.h>
#include <cstdint>
#include <math.h>

typedef __nv_bfloat16 bf16;

#define BATCH 8192
#define SDIM  268
#define HDIM  1024
#define RB    8
#define ADIM  256
#define ZDIM  8
#define PDIM  4
#define EDIM  4
#define KX    272   /* S+2 padded to multiple of 16 */

#define CDIV(a,b) (((a)+(b)-1)/(b))

#define EPI_NONE 0
#define EPI_RELU 1
#define EPI_TANH 2

// Pipeline / smem layout (per stage, bytes)
#define STG      20480
#define OFF_AL   6144          /* A: [128][24] bf16 = 6144B each (hi, lo) */
#define OFF_B    12288         /* B: [128][16] bf16 = 4096B each (hi, lo) */
#define OFF_BL   4096
#define NSTAGE   3
#define SMEM_DYN (NSTAGE * STG)   /* 61440 B */

// ---------------------------------------------------------------------------
// Scratch (static __device__ arrays; no allocation anywhere)
// ---------------------------------------------------------------------------
__device__ __align__(16) bf16 g_xh[BATCH*KX],   g_xl[BATCH*KX];
__device__ __align__(16) bf16 g_hh[BATCH*HDIM], g_hl[BATCH*HDIM];
__device__ __align__(16) bf16 g_uh[BATCH*HDIM], g_ul[BATCH*HDIM];
__device__ __align__(16) bf16 g_vh[BATCH*ADIM], g_vl[BATCH*ADIM];
__device__ __align__(16) float g_dh[BATCH*ADIM];
__device__ __align__(16) float g_dloc[BATCH*ZDIM];

__device__ __align__(16) bf16 g_W0h[HDIM*KX],       g_W0l[HDIM*KX];
__device__ __align__(16) bf16 g_W1h[RB*HDIM*HDIM],  g_W1l[RB*HDIM*HDIM];
__device__ __align__(16) bf16 g_W2h[RB*HDIM*HDIM],  g_W2l[RB*HDIM*HDIM];
__device__ __align__(16) bf16 g_Wfh[SDIM*HDIM],     g_Wfl[SDIM*HDIM];
__device__ __align__(16) bf16 g_TIh[ADIM*ADIM],     g_TIl[ADIM*ADIM];
__device__ __align__(16) bf16 g_TOh[ADIM*ADIM],     g_TOl[ADIM*ADIM];

// ---------------------------------------------------------------------------
// Helpers
// ---------------------------------------------------------------------------
__device__ __forceinline__ float tanh_fast(float x) {
    float e = __expf(2.0f * x);
    return 1.0f - __fdividef(2.0f, e + 1.0f);   // NaN-safe
}
__device__ __forceinline__ uint32_t smem_u32(const void* p) {
    uint32_t a;
    asm("{ .reg .u64 t; cvta.to.shared.u64 t, %1; cvt.u32.u64 %0, t; }" : "=r"(a) : "l"(p));
    return a;
}
__device__ __forceinline__ void ldm4(unsigned r[4], unsigned addr) {
    asm volatile("ldmatrix.sync.aligned.m8n8.x4.shared.b16 {%0,%1,%2,%3}, [%4];"
                 : "=r"(r[0]), "=r"(r[1]), "=r"(r[2]), "=r"(r[3]) : "r"(addr));
}
__device__ __forceinline__ void ldm2(unsigned r[2], unsigned addr) {
    asm volatile("ldmatrix.sync.aligned.m8n8.x2.shared.b16 {%0,%1}, [%2];"
                 : "=r"(r[0]), "=r"(r[1]) : "r"(addr));
}
__device__ __forceinline__ void mma_bf16(float c[4], const unsigned a[4], const unsigned b[2]) {
    asm volatile(
        "mma.sync.aligned.m16n8k16.row.col.f32.bf16.bf16.f32 "
        "{%0,%1,%2,%3}, {%4,%5,%6,%7}, {%8,%9}, {%0,%1,%2,%3};"
        : "+f"(c[0]), "+f"(c[1]), "+f"(c[2]), "+f"(c[3])
        : "r"(a[0]), "r"(a[1]), "r"(a[2]), "r"(a[3]), "r"(b[0]), "r"(b[1]));
}
__device__ __forceinline__ void cpa16(uint32_t dst, const void* src, unsigned n) {
    asm volatile("cp.async.cg.shared.global [%0], [%1], 16, %2;"
                 :: "r"(dst), "l"(src), "r"(n));
}
#define CP_COMMIT() asm volatile("cp.async.commit_group;" ::: "memory")
#define CP_WAIT1()  asm volatile("cp.async.wait_group 1;"  ::: "memory")
#define CP_WAIT0()  asm volatile("cp.async.wait_group 0;"  ::: "memory")

// ---------------------------------------------------------------------------
// GEMM: C(MxN) = act( (Ah+Al)(MxK) @ (Bh+Bl)^T + bias [+ (ADh+ADl)] )
// All operands bf16 hi/lo pairs, K-major row-major. 3-MMA split hh+hl+lh.
// Output: f32 (Cf) or bf16 hi/lo pair (Ch/Cl).
// CTA 128x128, 256 thr, warp grid 2x4, warp tile 64x32.
// cp.async 3-stage pipeline, K chunk 16, 2 CTAs/SM.
// ---------------------------------------------------------------------------
__global__ void __launch_bounds__(256, 2)
gemm_mma(const bf16* __restrict__ Ah_, const bf16* __restrict__ Al_, int lda,
         const bf16* __restrict__ Bh_, const bf16* __restrict__ Bl_, int ldb,
         const float* __restrict__ bias,
         const bf16* __restrict__ ADh, const bf16* __restrict__ ADl, int ldad,
         float* __restrict__ Cf, bf16* __restrict__ Ch, bf16* __restrict__ Cl,
         int ldc, int N, int K, int epi)
{
    extern __shared__ __align__(16) char smem[];
    const uint32_t sb = smem_u32(smem);

    const int tid    = threadIdx.x;
    const int lane   = tid & 31;
    const int wid    = tid >> 5;
    const int warpM  = wid >> 2;
    const int warpN  = wid & 3;
    const int blockM = blockIdx.y * 128;
    const int blockN = blockIdx.x * 128;

    // staging map: thread -> (row = tid/2, 8-elem half = tid&1)
    const int sRow  = tid >> 1;
    const int sHalf = tid & 1;
    const uint32_t dA = sb + (uint32_t)(sRow * 48 + sHalf * 16);
    const uint32_t dB = sb + OFF_B + (uint32_t)(sRow * 32 + sHalf * 16);

    const bf16* pAh = Ah_ + (size_t)(blockM + sRow) * lda + sHalf * 8;
    const bf16* pAl = Al_ + (size_t)(blockM + sRow) * lda + sHalf * 8;
    const int   nG  = blockN + sRow;
    const bool  bOk = nG < N;
    const int   nC  = bOk ? nG : 0;
    const bf16* pBh = Bh_ + (size_t)nC * ldb + sHalf * 8;
    const bf16* pBl = Bl_ + (size_t)nC * ldb + sHalf * 8;
    const unsigned bsz = bOk ? 16u : 0u;

    // ldmatrix offsets (within a stage)
    unsigned aOff[4], bOff[4];
    {
        const int r  = lane & 15;
        const int ko = (lane >> 4) * 8;
        #pragma unroll
        for (int mt = 0; mt < 4; ++mt)
            aOff[mt] = (unsigned)(((warpM * 64 + mt * 16 + r) * 24 + ko) * 2);
        const int rb  = lane & 7;
        const int kob = ((lane >> 3) & 1) * 8;
        #pragma unroll
        for (int nt = 0; nt < 4; ++nt)
            bOff[nt] = (unsigned)(((warpN * 32 + nt * 8 + rb) * 16 + kob) * 2);
    }

    float acc[4][4][4];
    #pragma unroll
    for (int mt = 0; mt < 4; ++mt)
        #pragma unroll
        for (int nt = 0; nt < 4; ++nt)
            #pragma unroll
            for (int i = 0; i < 4; ++i) acc[mt][nt][i] = 0.0f;

    const int nk = K / 16;

    // prologue: stages 0,1
    {
        cpa16(dA,                       pAh,     16u);
        cpa16(dA + OFF_AL,              pAl,     16u);
        cpa16(dB,                       pBh,     bsz);
        cpa16(dB + OFF_BL,              pBl,     bsz);
        CP_COMMIT();
        if (nk > 1) {
            cpa16(dA + STG,             pAh + 16, 16u);
            cpa16(dA + STG + OFF_AL,    pAl + 16, 16u);
            cpa16(dB + STG,             pBh + 16, bsz);
            cpa16(dB + STG + OFF_BL,    pBl + 16, bsz);
        }
        CP_COMMIT();
    }

    int cs = 0;          // compute stage slot
    int ns = 2;          // next issue slot
    for (int kt = 0; kt < nk; ++kt) {
        CP_WAIT1();              // chunk kt landed
        __syncthreads();         // also fences prev compute reads of slot ns

        // issue chunk kt+2 into slot ns (slot was consumed at iter kt-1)
        if (kt + 2 < nk) {
            const int k2 = (kt + 2) * 16;
            const uint32_t so = (uint32_t)(ns * STG);
            cpa16(dA + so,          pAh + k2, 16u);
            cpa16(dA + so + OFF_AL, pAl + k2, 16u);
            cpa16(dB + so,          pBh + k2, bsz);
            cpa16(dB + so + OFF_BL, pBl + k2, bsz);
        }
        CP_COMMIT();

        // compute chunk kt from slot cs
        {
            const uint32_t so = (uint32_t)(cs * STG);
            unsigned Ahf[4][4], Alf[4][4];
            #pragma unroll
            for (int mt = 0; mt < 4; ++mt) {
                ldm4(Ahf[mt], sb + so + aOff[mt]);
                ldm4(Alf[mt], sb + so + OFF_AL + aOff[mt]);
            }
            #pragma unroll
            for (int nt = 0; nt < 4; ++nt) {
                unsigned Bhf[2], Blf[2];
                ldm2(Bhf, sb + so + OFF_B + bOff[nt]);
                ldm2(Blf, sb + so + OFF_B + OFF_BL + bOff[nt]);
                #pragma unroll
                for (int mt = 0; mt < 4; ++mt) {
                    mma_bf16(acc[mt][nt], Ahf[mt], Bhf);
                    mma_bf16(acc[mt][nt], Ahf[mt], Blf);
                    mma_bf16(acc[mt][nt], Alf[mt], Bhf);
                }
            }
        }

        cs = (cs == NSTAGE - 1) ? 0 : cs + 1;
        ns = (ns == NSTAGE - 1) ? 0 : ns + 1;
    }
    CP_WAIT0();   // retire any tail groups before exit

    // ---- epilogue ----
    const int g = lane >> 2, q = lane & 3;
    #pragma unroll
    for (int mt = 0; mt < 4; ++mt) {
        #pragma unroll
        for (int nt = 0; nt < 4; ++nt) {
            const int row0 = blockM + warpM * 64 + mt * 16 + g;
            const int col  = blockN + warpN * 32 + nt * 8 + q * 2;
            const bool c0 = col < N, c1 = (col + 1) < N;
            const float b0v = c0 ? bias[col] : 0.0f;
            const float b1v = c1 ? bias[col + 1] : 0.0f;
            #pragma unroll
            for (int rr = 0; rr < 2; ++rr) {
                const int r = row0 + rr * 8;
                float v0 = acc[mt][nt][rr * 2 + 0] + b0v;
                float v1 = acc[mt][nt][rr * 2 + 1] + b1v;
                if (ADh) {
                    const size_t o = (size_t)r * ldad + col;
                    if (c0) v0 += __bfloat162float(ADh[o])     + __bfloat162float(ADl[o]);
                    if (c1) v1 += __bfloat162float(ADh[o + 1]) + __bfloat162float(ADl[o + 1]);
                }
                if (epi == EPI_RELU)      { v0 = fmaxf(v0, 0.0f); v1 = fmaxf(v1, 0.0f); }
                else if (epi == EPI_TANH) { v0 = tanh_fast(v0);   v1 = tanh_fast(v1);   }
                const size_t oc = (size_t)r * ldc + col;
                if (Cf) {
                    if (c0) Cf[oc]     = v0;
                    if (c1) Cf[oc + 1] = v1;
                } else {
                    bf16 h0 = __float2bfloat16(v0);
                    bf16 h1 = __float2bfloat16(v1);
                    bf16 l0 = __float2bfloat16(v0 - __bfloat162float(h0));
                    bf16 l1 = __float2bfloat16(v1 - __bfloat162float(h1));
                    if (c0 && c1) {
                        *(__nv_bfloat162*)(Ch + oc) = __halves2bfloat162(h0, h1);
                        *(__nv_bfloat162*)(Cl + oc) = __halves2bfloat162(l0, l1);
                    } else if (c0) {
                        Ch[oc] = h0; Cl[oc] = l0;
                    }
                }
            }
        }
    }
}

// ---------------------------------------------------------------------------
// Prologue kernels
// ---------------------------------------------------------------------------
__global__ void split4_kernel(const float* __restrict__ src,
                              bf16* __restrict__ hi, bf16* __restrict__ lo, int n4)
{
    int i = blockIdx.x * blockDim.x + threadIdx.x;
    if (i >= n4) return;
    float4 v = ((const float4*)src)[i];
    float a[4] = {v.x, v.y, v.z, v.w};
    __nv_bfloat162* dh = (__nv_bfloat162*)hi;
    __nv_bfloat162* dl = (__nv_bfloat162*)lo;
    bf16 h[4], l[4];
    #pragma unroll
    for (int j = 0; j < 4; ++j) {
        h[j] = __float2bfloat16(a[j]);
        l[j] = __float2bfloat16(a[j] - __bfloat162float(h[j]));
    }
    dh[2*i]   = __halves2bfloat162(h[0], h[1]);
    dh[2*i+1] = __halves2bfloat162(h[2], h[3]);
    dl[2*i]   = __halves2bfloat162(l[0], l[1]);
    dl[2*i+1] = __halves2bfloat162(l[2], l[3]);
}

__global__ void splitW0_kernel(const float* __restrict__ W0,
                               bf16* __restrict__ hi, bf16* __restrict__ lo)
{
    int i = blockIdx.x * blockDim.x + threadIdx.x;
    if (i >= HDIM * KX) return;
    int row = i / KX, c = i % KX;
    float v = (c < SDIM + 2) ? W0[row * (SDIM + 2) + c] : 0.0f;
    bf16 h = __float2bfloat16(v);
    hi[i] = h;
    lo[i] = __float2bfloat16(v - __bfloat162float(h));
}

__global__ void buildx_kernel(const float* __restrict__ state,
                              const float* __restrict__ t,
                              bf16* __restrict__ xh, bf16* __restrict__ xl)
{
    int i = blockIdx.x * blockDim.x + threadIdx.x;
    if (i >= BATCH * KX) return;
    int b = i / KX, c = i % KX;
    float v;
    if (c < SDIM) v = state[b * SDIM + c];
    else if (c == SDIM)     { float ang = t[0] * 0.26179938779914943654f; v = sinf(ang); }
    else if (c == SDIM + 1) { float ang = t[0] * 0.26179938779914943654f; v = cosf(ang); }
    else v = 0.0f;
    bf16 h = __float2bfloat16(v);
    xh[i] = h;
    xl[i] = __float2bfloat16(v - __bfloat162float(h));
}

// ---------------------------------------------------------------------------
// Tiny loc path (exact fp32)
// ---------------------------------------------------------------------------
__global__ void loc_kernel(const float* __restrict__ state,
                           const float* __restrict__ loc_proj_w, const float* __restrict__ loc_proj_b,
                           const float* __restrict__ lp_in_w,    const float* __restrict__ lp_in_b,
                           const float* __restrict__ lp_out_w,   const float* __restrict__ lp_out_b,
                           const float* __restrict__ loc_back_w, const float* __restrict__ loc_back_b,
                           float* __restrict__ dloc)
{
    int b = blockIdx.x * blockDim.x + threadIdx.x;
    if (b >= BATCH) return;
    float loc[ZDIM];
    #pragma unroll
    for (int z = 0; z < ZDIM; ++z) loc[z] = state[b * SDIM + ADIM + z];
    float lp[EDIM];
    #pragma unroll
    for (int e = 0; e < EDIM; ++e) {
        float s = loc_proj_b[e];
        #pragma unroll
        for (int z = 0; z < ZDIM; ++z) s += loc_proj_w[e * ZDIM + z] * loc[z];
        lp[e] = s;
    }
    float v[EDIM];
    #pragma unroll
    for (int e = 0; e < EDIM; ++e) {
        float s = lp_in_b[2 * EDIM + e];
        #pragma unroll
        for (int j = 0; j < EDIM; ++j) s += lp_in_w[(2 * EDIM + e) * EDIM + j] * lp[j];
        v[e] = s;
    }
    float d[EDIM];
    #pragma unroll
    for (int e = 0; e < EDIM; ++e) {
        float s = lp_out_b[e];
        #pragma unroll
        for (int j = 0; j < EDIM; ++j) s += lp_out_w[e * EDIM + j] * v[j];
        d[e] = s - lp[e];
    }
    #pragma unroll
    for (int z = 0; z < ZDIM; ++z) {
        float s = loc_back_b[z];
        #pragma unroll
        for (int e = 0; e < EDIM; ++e) s += loc_back_w[z * EDIM + e] * d[e];
        dloc[b * ZDIM + z] = s;
    }
}

// out = core + 0.1 * delta
__global__ void combine_kernel(float* __restrict__ out,
                               const float* __restrict__ state,
                               const float* __restrict__ dh,
                               const float* __restrict__ dloc)
{
    int i = blockIdx.x * blockDim.x + threadIdx.x;
    if (i >= BATCH * SDIM) return;
    int b = i / SDIM, j = i % SDIM;
    float o = out[i];
    if (j < ADIM)              o += 0.1f * (dh[b * ADIM + j] - state[i]);
    else if (j < ADIM + ZDIM)  o += 0.1f * dloc[b * ZDIM + (j - ADIM)];
    out[i] = o;
}

// ---------------------------------------------------------------------------
// Launch
// ---------------------------------------------------------------------------
extern "C" void kernel_launch(void* const* d_in, const int* in_sizes, int n_in,
                              void* d_out, int out_size)
{
    const float* t          = (const float*)d_in[0];
    const float* state      = (const float*)d_in[1];
    const float* W0         = (const float*)d_in[2];
    const float* b0         = (const float*)d_in[3];
    const float* rW1        = (const float*)d_in[4];
    const float* rb1        = (const float*)d_in[5];
    const float* rW2        = (const float*)d_in[6];
    const float* rb2        = (const float*)d_in[7];
    const float* Wf         = (const float*)d_in[8];
    const float* bf_        = (const float*)d_in[9];
    const float* lp_in_w    = (const float*)d_in[10];
    const float* lp_in_b    = (const float*)d_in[11];
    const float* lp_out_w   = (const float*)d_in[12];
    const float* lp_out_b   = (const float*)d_in[13];
    const float* ta_in_w    = (const float*)d_in[14];
    const float* ta_in_b    = (const float*)d_in[15];
    const float* ta_out_w   = (const float*)d_in[16];
    const float* ta_out_b   = (const float*)d_in[17];
    const float* loc_proj_w = (const float*)d_in[18];
    const float* loc_proj_b = (const float*)d_in[19];
    const float* loc_back_w = (const float*)d_in[20];
    const float* loc_back_b = (const float*)d_in[21];
    float* out = (float*)d_out;

    bf16 *xh, *xl, *hh, *hl, *uh, *ul, *vh, *vl;
    float *dh, *dloc;
    bf16 *W0h, *W0l, *W1h, *W1l, *W2h, *W2l, *Wfh, *Wfl, *TIh, *TIl, *TOh, *TOl;
    cudaGetSymbolAddress((void**)&xh, g_xh);   cudaGetSymbolAddress((void**)&xl, g_xl);
    cudaGetSymbolAddress((void**)&hh, g_hh);   cudaGetSymbolAddress((void**)&hl, g_hl);
    cudaGetSymbolAddress((void**)&uh, g_uh);   cudaGetSymbolAddress((void**)&ul, g_ul);
    cudaGetSymbolAddress((void**)&vh, g_vh);   cudaGetSymbolAddress((void**)&vl, g_vl);
    cudaGetSymbolAddress((void**)&dh, g_dh);   cudaGetSymbolAddress((void**)&dloc, g_dloc);
    cudaGetSymbolAddress((void**)&W0h, g_W0h); cudaGetSymbolAddress((void**)&W0l, g_W0l);
    cudaGetSymbolAddress((void**)&W1h, g_W1h); cudaGetSymbolAddress((void**)&W1l, g_W1l);
    cudaGetSymbolAddress((void**)&W2h, g_W2h); cudaGetSymbolAddress((void**)&W2l, g_W2l);
    cudaGetSymbolAddress((void**)&Wfh, g_Wfh); cudaGetSymbolAddress((void**)&Wfl, g_Wfl);
    cudaGetSymbolAddress((void**)&TIh, g_TIh); cudaGetSymbolAddress((void**)&TIl, g_TIl);
    cudaGetSymbolAddress((void**)&TOh, g_TOh); cudaGetSymbolAddress((void**)&TOl, g_TOl);

    cudaFuncSetAttribute(gemm_mma, cudaFuncAttributeMaxDynamicSharedMemorySize, SMEM_DYN);

    // --- prologue: split weights to bf16 hi/lo, build x hi/lo ---
    {
        int n4;
        n4 = (RB * HDIM * HDIM) / 4;
        split4_kernel<<<CDIV(n4, 256), 256>>>(rW1, W1h, W1l, n4);
        split4_kernel<<<CDIV(n4, 256), 256>>>(rW2, W2h, W2l, n4);
        n4 = (SDIM * HDIM) / 4;
        split4_kernel<<<CDIV(n4, 256), 256>>>(Wf, Wfh, Wfl, n4);
        n4 = (ADIM * ADIM) / 4;
        split4_kernel<<<CDIV(n4, 256), 256>>>(ta_in_w + 2 * ADIM * ADIM, TIh, TIl, n4);
        split4_kernel<<<CDIV(n4, 256), 256>>>(ta_out_w, TOh, TOl, n4);
        splitW0_kernel<<<CDIV(HDIM * KX, 256), 256>>>(W0, W0h, W0l);
        buildx_kernel<<<CDIV(BATCH * KX, 256), 256>>>(state, t, xh, xl);
    }

    // --- main chain ---
    dim3 blk(256);
    dim3 gH(HDIM / 128, BATCH / 128);           // (8, 64)

    // h = relu(x @ W0^T + b0)   -> split
    gemm_mma<<<gH, blk, SMEM_DYN>>>(xh, xl, KX, W0h, W0l, KX, b0,
                                    nullptr, nullptr, 0,
                                    nullptr, hh, hl, HDIM, HDIM, KX, EPI_RELU);

    for (int i = 0; i < RB; ++i) {
        const size_t wo = (size_t)i * HDIM * HDIM;
        // u = tanh(h @ W1^T + b1)           -> split
        gemm_mma<<<gH, blk, SMEM_DYN>>>(hh, hl, HDIM, W1h + wo, W1l + wo, HDIM,
                                        rb1 + i * HDIM, nullptr, nullptr, 0,
                                        nullptr, uh, ul, HDIM, HDIM, HDIM, EPI_TANH);
        // h = tanh(u @ W2^T + b2 + h)       -> split (in-place safe: 1 thread per elem)
        gemm_mma<<<gH, blk, SMEM_DYN>>>(uh, ul, HDIM, W2h + wo, W2l + wo, HDIM,
                                        rb2 + i * HDIM, hh, hl, HDIM,
                                        nullptr, hh, hl, HDIM, HDIM, HDIM, EPI_TANH);
    }

    // core = h @ Wf^T + bf  -> f32 out
    dim3 gF(CDIV(SDIM, 128), BATCH / 128);      // (3, 64)
    gemm_mma<<<gF, blk, SMEM_DYN>>>(hh, hl, HDIM, Wfh, Wfl, HDIM, bf_,
                                    nullptr, nullptr, 0,
                                    out, nullptr, nullptr, SDIM, SDIM, HDIM, EPI_NONE);

    // --- independent side path (A = state cols of x) ---
    dim3 gT(ADIM / 128, BATCH / 128);           // (2, 64)
    gemm_mma<<<gT, blk, SMEM_DYN>>>(xh, xl, KX, TIh, TIl, ADIM, ta_in_b + 2 * ADIM,
                                    nullptr, nullptr, 0,
                                    nullptr, vh, vl, ADIM, ADIM, ADIM, EPI_NONE);
    gemm_mma<<<gT, blk, SMEM_DYN>>>(vh, vl, ADIM, TOh, TOl, ADIM, ta_out_b,
                                    nullptr, nullptr, 0,
                                    dh, nullptr, nullptr, ADIM, ADIM, ADIM, EPI_NONE);
    loc_kernel<<<CDIV(BATCH, 256), 256>>>(state, loc_proj_w, loc_proj_b,
                                          lp_in_w, lp_in_b, lp_out_w, lp_out_b,
                                          loc_back_w, loc_back_b, dloc);

    // --- final combine ---
    combine_kernel<<<CDIV(BATCH * SDIM, 256), 256>>>(out, state, dh, dloc);
}